// round 1
// baseline (speedup 1.0000x reference)
#include <cuda_runtime.h>
#include <math.h>

#define NQ 8192
#define NC 8192
#define DIM 256
#define BQ 64
#define BC 128
#define KT 16
#define XS_STRIDE (BQ + 4)                  // 68
#define ES_STRIDE (BC + 4)                  // 132
#define XS_FLOATS (DIM * XS_STRIDE)         // 17408
#define ES_FLOATS (2 * KT * ES_STRIDE)      // 4224
#define SMEM_BYTES ((XS_FLOATS + ES_FLOATS) * 4)   // 86528 B

__device__ float g_enorm[NC];
__device__ int   g_indices[NQ];
__device__ int   g_counts[NC];
__device__ float g_partial[NQ];

// ---------------------------------------------------------------------------
// k_init: zero histogram counts + compute ||e||^2 per codebook row.
// grid = 1024 blocks x 256 threads; one warp per codebook row (8 rows/block).
// ---------------------------------------------------------------------------
__global__ void k_init(const float* __restrict__ cb) {
    int gid = blockIdx.x * blockDim.x + threadIdx.x;
    if (gid < NC) g_counts[gid] = 0;

    int warp = threadIdx.x >> 5;
    int lane = threadIdx.x & 31;
    int code = blockIdx.x * 8 + warp;
    const float4* row = (const float4*)(cb + (size_t)code * DIM);
    float s = 0.f;
    float4 v = row[lane];
    s += v.x * v.x + v.y * v.y + v.z * v.z + v.w * v.w;
    v = row[lane + 32];
    s += v.x * v.x + v.y * v.y + v.z * v.z + v.w * v.w;
    #pragma unroll
    for (int off = 16; off > 0; off >>= 1)
        s += __shfl_down_sync(0xffffffffu, s, off);
    if (lane == 0) g_enorm[code] = s;
}

// ---------------------------------------------------------------------------
// k_argmin: fused fp32 GEMM (X @ E^T) + running row-argmin of (||e||^2 - 2 dot).
// Block: 256 threads = 16(tx, codes) x 16(ty, queries). Thread tile 4q x 8c.
// Query tile (64x256) fully resident in SMEM; codebook streamed in
// double-buffered 128x16 chunks.
// ---------------------------------------------------------------------------
__global__ __launch_bounds__(256) void k_argmin(const float* __restrict__ X,
                                                const float* __restrict__ E) {
    extern __shared__ float sm[];
    float* Xs = sm;                  // [DIM][XS_STRIDE], Xs[k][q]
    float* Es = sm + XS_FLOATS;      // [2][KT][ES_STRIDE], Es[buf][k][c]

    const int tid = threadIdx.x;
    const int tx  = tid & 15;        // code direction
    const int ty  = tid >> 4;        // query direction
    const int q0  = blockIdx.x * BQ;

    // --- Load full query tile into SMEM (transposed: Xs[k][q]) ---
    #pragma unroll
    for (int i = 0; i < 16; i++) {
        int idx = tid + i * 256;     // 0..4095 float4 slots
        int r   = idx >> 6;          // query row 0..63
        int s4  = idx & 63;          // float4 index in row
        float4 v = *(const float4*)(X + (size_t)(q0 + r) * DIM + s4 * 4);
        Xs[(s4 * 4 + 0) * XS_STRIDE + r] = v.x;
        Xs[(s4 * 4 + 1) * XS_STRIDE + r] = v.y;
        Xs[(s4 * 4 + 2) * XS_STRIDE + r] = v.z;
        Xs[(s4 * 4 + 3) * XS_STRIDE + r] = v.w;
    }
    __syncthreads();

    float best[4];
    int   bidx[4];
    #pragma unroll
    for (int i = 0; i < 4; i++) { best[i] = INFINITY; bidx[i] = 0; }

    const int er = tid >> 2;         // 0..63 (code row within half-tile)
    const int es = tid & 3;          // float4 segment in k-chunk

    for (int c0 = 0; c0 < NC; c0 += BC) {
        float acc[4][8];
        #pragma unroll
        for (int i = 0; i < 4; i++)
            #pragma unroll
            for (int j = 0; j < 8; j++) acc[i][j] = 0.f;

        // prologue: load chunk 0
        float4 ve0 = *(const float4*)(E + (size_t)(c0 + er)      * DIM + es * 4);
        float4 ve1 = *(const float4*)(E + (size_t)(c0 + 64 + er) * DIM + es * 4);
        __syncthreads();             // previous tile finished reading Es
        {
            float* dst = Es;         // buffer 0
            dst[(es * 4 + 0) * ES_STRIDE + er] = ve0.x;
            dst[(es * 4 + 1) * ES_STRIDE + er] = ve0.y;
            dst[(es * 4 + 2) * ES_STRIDE + er] = ve0.z;
            dst[(es * 4 + 3) * ES_STRIDE + er] = ve0.w;
            dst[(es * 4 + 0) * ES_STRIDE + 64 + er] = ve1.x;
            dst[(es * 4 + 1) * ES_STRIDE + 64 + er] = ve1.y;
            dst[(es * 4 + 2) * ES_STRIDE + 64 + er] = ve1.z;
            dst[(es * 4 + 3) * ES_STRIDE + 64 + er] = ve1.w;
        }
        __syncthreads();

        #pragma unroll 1
        for (int kc = 0; kc < DIM / KT; kc++) {
            if (kc < DIM / KT - 1) {
                int k0 = (kc + 1) * KT;
                ve0 = *(const float4*)(E + (size_t)(c0 + er)      * DIM + k0 + es * 4);
                ve1 = *(const float4*)(E + (size_t)(c0 + 64 + er) * DIM + k0 + es * 4);
            }
            const float* Eb = Es + (kc & 1) * (KT * ES_STRIDE);
            const float* Xb = Xs + kc * KT * XS_STRIDE;
            #pragma unroll
            for (int k = 0; k < KT; k++) {
                float4 a  = *(const float4*)(Xb + k * XS_STRIDE + ty * 4);
                float4 b0 = *(const float4*)(Eb + k * ES_STRIDE + tx * 8);
                float4 b1 = *(const float4*)(Eb + k * ES_STRIDE + tx * 8 + 4);
                float av[4] = {a.x, a.y, a.z, a.w};
                float bv[8] = {b0.x, b0.y, b0.z, b0.w, b1.x, b1.y, b1.z, b1.w};
                #pragma unroll
                for (int i = 0; i < 4; i++)
                    #pragma unroll
                    for (int j = 0; j < 8; j++)
                        acc[i][j] = fmaf(av[i], bv[j], acc[i][j]);
            }
            if (kc < DIM / KT - 1) {
                float* dst = Es + ((kc + 1) & 1) * (KT * ES_STRIDE);
                dst[(es * 4 + 0) * ES_STRIDE + er] = ve0.x;
                dst[(es * 4 + 1) * ES_STRIDE + er] = ve0.y;
                dst[(es * 4 + 2) * ES_STRIDE + er] = ve0.z;
                dst[(es * 4 + 3) * ES_STRIDE + er] = ve0.w;
                dst[(es * 4 + 0) * ES_STRIDE + 64 + er] = ve1.x;
                dst[(es * 4 + 1) * ES_STRIDE + 64 + er] = ve1.y;
                dst[(es * 4 + 2) * ES_STRIDE + 64 + er] = ve1.z;
                dst[(es * 4 + 3) * ES_STRIDE + 64 + er] = ve1.w;
                __syncthreads();
            }
        }

        // epilogue: distance = ||e||^2 - 2*dot (||x||^2 constant per query)
        int cb = c0 + tx * 8;
        #pragma unroll
        for (int j = 0; j < 8; j++) {
            float en = g_enorm[cb + j];
            #pragma unroll
            for (int i = 0; i < 4; i++) {
                float d = en - 2.f * acc[i][j];
                if (d < best[i]) { best[i] = d; bidx[i] = cb + j; }
            }
        }
    }

    // --- Cross-thread argmin reduce (16 threads per query), reusing Es area ---
    __syncthreads();
    float* rv = Es;                  // 1024 floats
    int*   ri = (int*)(Es + 1024);   // 1024 ints
    #pragma unroll
    for (int i = 0; i < 4; i++) {
        rv[(ty * 4 + i) * 16 + tx] = best[i];
        ri[(ty * 4 + i) * 16 + tx] = bidx[i];
    }
    __syncthreads();
    if (tid < BQ) {
        float bv = rv[tid * 16];
        int   bi = ri[tid * 16];
        #pragma unroll
        for (int t = 1; t < 16; t++) {
            float v  = rv[tid * 16 + t];
            int   id = ri[tid * 16 + t];
            if (v < bv || (v == bv && id < bi)) { bv = v; bi = id; }
        }
        g_indices[q0 + tid] = bi;
    }
}

// ---------------------------------------------------------------------------
// k_gather: quantized output (mimics x + (q - x) rounding of the STE),
// deterministic per-query loss partials, int histogram.
// grid = 8192 blocks x 256 threads (one block per query row).
// ---------------------------------------------------------------------------
__global__ void k_gather(const float* __restrict__ X, const float* __restrict__ E,
                         float* __restrict__ out) {
    __shared__ float red[256];
    int n = blockIdx.x;
    int d = threadIdx.x;
    int idx = g_indices[n];
    float q = E[(size_t)idx * DIM + d];
    float x = X[(size_t)n * DIM + d];
    float diff = q - x;
    out[(size_t)n * DIM + d] = x + diff;   // straight-through estimator numerics
    red[d] = diff * diff;
    __syncthreads();
    #pragma unroll
    for (int off = 128; off > 0; off >>= 1) {
        if (d < off) red[d] += red[d + off];
        __syncthreads();
    }
    if (d == 0) {
        g_partial[n] = red[0];
        atomicAdd(&g_counts[idx], 1);
    }
}

// ---------------------------------------------------------------------------
// k_final: deterministic reduction of loss partials + perplexity, writes the
// two scalar outputs.
// ---------------------------------------------------------------------------
__global__ void k_final(float* __restrict__ out, int out_size) {
    __shared__ float sm[256];
    int t = threadIdx.x;

    float s = 0.f;
    for (int i = t; i < NQ; i += 256) s += g_partial[i];
    sm[t] = s;
    __syncthreads();
    #pragma unroll
    for (int off = 128; off > 0; off >>= 1) {
        if (t < off) sm[t] += sm[t + off];
        __syncthreads();
    }
    float total = sm[0];
    __syncthreads();

    float h = 0.f;
    for (int i = t; i < NC; i += 256) {
        float p = (float)g_counts[i] * (1.0f / (float)NQ);
        h += p * logf(p + 1e-10f);
    }
    sm[t] = h;
    __syncthreads();
    #pragma unroll
    for (int off = 128; off > 0; off >>= 1) {
        if (t < off) sm[t] += sm[t + off];
        __syncthreads();
    }

    if (t == 0) {
        float mean_sq = total / (float)((size_t)NQ * DIM);
        float e_latent = mean_sq;
        float q_latent = mean_sq;
        float loss = q_latent + 0.25f * e_latent;
        float perplexity = expf(-sm[0]);
        if (out_size >= NQ * DIM + 2) {
            out[(size_t)NQ * DIM]     = loss;
            out[(size_t)NQ * DIM + 1] = perplexity;
        }
    }
}

// ---------------------------------------------------------------------------
extern "C" void kernel_launch(void* const* d_in, const int* in_sizes, int n_in,
                              void* d_out, int out_size) {
    const float* X = (const float*)d_in[0];   // inputs [32,256,256] -> [8192,256]
    const float* E = (const float*)d_in[1];   // codebook [8192,256]
    float* out = (float*)d_out;

    cudaFuncSetAttribute(k_argmin, cudaFuncAttributeMaxDynamicSharedMemorySize,
                         SMEM_BYTES);

    k_init<<<NC / 8, 256>>>(E);
    k_argmin<<<NQ / BQ, 256, SMEM_BYTES>>>(X, E);
    k_gather<<<NQ, 256>>>(X, E, out);
    k_final<<<1, 256>>>(out, out_size);
}

// round 3
// speedup vs baseline: 2.5709x; 2.5709x over previous
#include <cuda_runtime.h>
#include <math.h>
#include <stdint.h>

#define NQ 8192
#define NC 8192
#define DIM 256

#define XS_STRIDE 260                       // 256 + 4 pad: bank = (4*gid+tig)%32, conflict-free
#define ES_STRIDE 36                        // 32 + 4 pad:  bank = (4*gid+tig)%32, conflict-free
#define XS_FLOATS (128 * XS_STRIDE)         // 33280
#define ES_FLOATS (2 * 128 * ES_STRIDE)     // 9216
#define SMEM_BYTES ((XS_FLOATS + ES_FLOATS) * 4)   // 170,  -> 169984 B

__device__ float g_enorm[NC];
__device__ int   g_counts[NC];
__device__ float g_partial[NQ];
__device__ float g_bestv[2 * NQ];
__device__ int   g_besti[2 * NQ];

// ---------------------------------------------------------------------------
// m16n8k8 tf32 mma (plain sm_103-legal, legacy HMMA path)
// ---------------------------------------------------------------------------
__device__ __forceinline__ void mma8(float* c, const uint32_t* a, uint32_t b0, uint32_t b1) {
    asm volatile(
        "mma.sync.aligned.m16n8k8.row.col.f32.tf32.tf32.f32 "
        "{%0,%1,%2,%3}, {%4,%5,%6,%7}, {%8,%9}, {%0,%1,%2,%3};"
        : "+f"(c[0]), "+f"(c[1]), "+f"(c[2]), "+f"(c[3])
        : "r"(a[0]), "r"(a[1]), "r"(a[2]), "r"(a[3]), "r"(b0), "r"(b1));
}

// truncation split: hi = top-10-mantissa bits (what HMMA tf32 reads), lo = exact residual
__device__ __forceinline__ void split_tf(float v, uint32_t& hi, uint32_t& lo) {
    hi = __float_as_uint(v) & 0xFFFFE000u;
    lo = __float_as_uint(v - __uint_as_float(hi));
}

// ---------------------------------------------------------------------------
// k_init: ||e||^2 per codebook row (1 warp/row) + zero histogram.
// ---------------------------------------------------------------------------
__global__ void k_init(const float* __restrict__ cb) {
    int gid = blockIdx.x * blockDim.x + threadIdx.x;
    if (gid < NC) g_counts[gid] = 0;

    int warp = threadIdx.x >> 5;
    int lane = threadIdx.x & 31;
    int code = blockIdx.x * 8 + warp;
    const float4* row = (const float4*)(cb + (size_t)code * DIM);
    float s = 0.f;
    float4 v = row[lane];
    s += v.x * v.x + v.y * v.y + v.z * v.z + v.w * v.w;
    v = row[lane + 32];
    s += v.x * v.x + v.y * v.y + v.z * v.z + v.w * v.w;
    #pragma unroll
    for (int off = 16; off > 0; off >>= 1)
        s += __shfl_down_sync(0xffffffffu, s, off);
    if (lane == 0) g_enorm[code] = s;
}

// ---------------------------------------------------------------------------
// k_gemm: 3xTF32 mma.sync distance GEMM + fused per-thread argmin.
// Grid (64 q-tiles, 2 strips) x 256 threads. CTA tile: 128 q x 4096 codes.
// Warp layout: 4 warps along m (32 rows each), 2 along n (64 cols each).
// ---------------------------------------------------------------------------
__global__ __launch_bounds__(256, 1) void k_gemm(const float* __restrict__ X,
                                                 const float* __restrict__ E) {
    extern __shared__ float sm[];
    float* Xs = sm;                       // [128][XS_STRIDE]
    float* Es = sm + XS_FLOATS;           // [2][128][ES_STRIDE]

    const int tid   = threadIdx.x;
    const int lane  = tid & 31;
    const int wid   = tid >> 5;
    const int warpm = wid & 3;            // 0..3
    const int warpn = wid >> 2;           // 0..1
    const int gid   = lane >> 2;          // 0..7
    const int tig   = lane & 3;           // 0..3
    const int q0    = blockIdx.x * 128;
    const int cbase0 = blockIdx.y * 4096;

    // ---- load X tile (fp32, padded) ----
    #pragma unroll
    for (int i = 0; i < 32; i++) {
        int idx = tid + i * 256;          // 0..8191
        int r = idx >> 6;                 // row 0..127
        int j = idx & 63;                 // float4 slot
        float4 v = *(const float4*)(X + (size_t)(q0 + r) * DIM + j * 4);
        *(float4*)(Xs + r * XS_STRIDE + j * 4) = v;
    }

    // ---- prologue: stage E chunk 0 ----
    {
        #pragma unroll
        for (int j = 0; j < 4; j++) {
            int i = tid + j * 256;        // 0..1023 float4 slots
            int row = i >> 3;
            int f4 = i & 7;
            float4 v = *(const float4*)(E + (size_t)(cbase0 + row) * DIM + f4 * 4);
            *(float4*)(Es + row * ES_STRIDE + f4 * 4) = v;
        }
    }
    __syncthreads();

    float best[4];
    int   bidx[4];
    #pragma unroll
    for (int i = 0; i < 4; i++) { best[i] = INFINITY; bidx[i] = 0; }

    for (int ct = 0; ct < 32; ct++) {
        float c[2][8][4];
        #pragma unroll
        for (int mt = 0; mt < 2; mt++)
            #pragma unroll
            for (int nt = 0; nt < 8; nt++)
                #pragma unroll
                for (int r = 0; r < 4; r++) c[mt][nt][r] = 0.f;

        for (int kc = 0; kc < 8; kc++) {
            const int cc = ct * 8 + kc;
            const int buf = cc & 1;

            // prefetch next chunk (possibly next ctile's chunk 0) into regs
            float4 pref[4];
            const bool hasnext = (cc < 255);
            if (hasnext) {
                const int nct = (cc + 1) >> 3;
                const int nkc = (cc + 1) & 7;
                const int c0n = cbase0 + nct * 128;
                #pragma unroll
                for (int j = 0; j < 4; j++) {
                    int i = tid + j * 256;
                    int row = i >> 3;
                    int f4 = i & 7;
                    pref[j] = *(const float4*)(E + (size_t)(c0n + row) * DIM + nkc * 32 + f4 * 4);
                }
            }

            // ---- compute on staged buffer ----
            const float* Eb = Es + buf * 128 * ES_STRIDE;
            #pragma unroll
            for (int k8 = 0; k8 < 4; k8++) {
                const int kb = kc * 32 + k8 * 8;   // global k for A
                const int kk = k8 * 8;             // local k for B

                uint32_t ah[2][4], al[2][4];
                #pragma unroll
                for (int mt = 0; mt < 2; mt++) {
                    const int r = warpm * 32 + mt * 16 + gid;
                    float a0 = Xs[r * XS_STRIDE + kb + tig];
                    float a1 = Xs[(r + 8) * XS_STRIDE + kb + tig];
                    float a2 = Xs[r * XS_STRIDE + kb + 4 + tig];
                    float a3 = Xs[(r + 8) * XS_STRIDE + kb + 4 + tig];
                    split_tf(a0, ah[mt][0], al[mt][0]);
                    split_tf(a1, ah[mt][1], al[mt][1]);
                    split_tf(a2, ah[mt][2], al[mt][2]);
                    split_tf(a3, ah[mt][3], al[mt][3]);
                }
                #pragma unroll
                for (int nt = 0; nt < 8; nt++) {
                    const int n = warpn * 64 + nt * 8 + gid;
                    float b0 = Eb[n * ES_STRIDE + kk + tig];
                    float b1 = Eb[n * ES_STRIDE + kk + 4 + tig];
                    uint32_t bh0, bl0, bh1, bl1;
                    split_tf(b0, bh0, bl0);
                    split_tf(b1, bh1, bl1);
                    // xh*eh
                    mma8(c[0][nt], ah[0], bh0, bh1);
                    mma8(c[1][nt], ah[1], bh0, bh1);
                    // xh*el
                    mma8(c[0][nt], ah[0], bl0, bl1);
                    mma8(c[1][nt], ah[1], bl0, bl1);
                    // xl*eh
                    mma8(c[0][nt], al[0], bh0, bh1);
                    mma8(c[1][nt], al[1], bh0, bh1);
                }
            }

            // ---- stage prefetched chunk into the other buffer ----
            if (hasnext) {
                float* Ed = Es + ((cc + 1) & 1) * 128 * ES_STRIDE;
                #pragma unroll
                for (int j = 0; j < 4; j++) {
                    int i = tid + j * 256;
                    int row = i >> 3;
                    int f4 = i & 7;
                    *(float4*)(Ed + row * ES_STRIDE + f4 * 4) = pref[j];
                }
            }
            __syncthreads();
        }

        // ---- fused argmin epilogue for this ctile (regs only) ----
        const int cb = cbase0 + ct * 128 + warpn * 64;
        #pragma unroll
        for (int nt = 0; nt < 8; nt++) {
            const int col0 = cb + nt * 8 + tig * 2;
            const float en0 = __ldg(&g_enorm[col0]);
            const float en1 = __ldg(&g_enorm[col0 + 1]);
            #pragma unroll
            for (int mt = 0; mt < 2; mt++) {
                float d;
                d = fmaf(-2.f, c[mt][nt][0], en0);
                if (d < best[mt * 2 + 0]) { best[mt * 2 + 0] = d; bidx[mt * 2 + 0] = col0; }
                d = fmaf(-2.f, c[mt][nt][1], en1);
                if (d < best[mt * 2 + 0]) { best[mt * 2 + 0] = d; bidx[mt * 2 + 0] = col0 + 1; }
                d = fmaf(-2.f, c[mt][nt][2], en0);
                if (d < best[mt * 2 + 1]) { best[mt * 2 + 1] = d; bidx[mt * 2 + 1] = col0; }
                d = fmaf(-2.f, c[mt][nt][3], en1);
                if (d < best[mt * 2 + 1]) { best[mt * 2 + 1] = d; bidx[mt * 2 + 1] = col0 + 1; }
            }
        }
    }

    // ---- cross-thread argmin reduce: 8 contributors per query row ----
    __syncthreads();
    float* rv = Es;                        // 128*8 floats
    int*   ri = (int*)(Es + 1024);         // 128*8 ints
    const int slot = warpn * 4 + tig;
    #pragma unroll
    for (int mt = 0; mt < 2; mt++)
        #pragma unroll
        for (int rh = 0; rh < 2; rh++) {
            const int row = warpm * 32 + mt * 16 + rh * 8 + gid;
            rv[row * 8 + slot] = best[mt * 2 + rh];
            ri[row * 8 + slot] = bidx[mt * 2 + rh];
        }
    __syncthreads();
    if (tid < 128) {
        float bv = rv[tid * 8];
        int   bi = ri[tid * 8];
        #pragma unroll
        for (int s = 1; s < 8; s++) {
            float v = rv[tid * 8 + s];
            int   i = ri[tid * 8 + s];
            if (v < bv || (v == bv && i < bi)) { bv = v; bi = i; }
        }
        g_bestv[blockIdx.y * NQ + q0 + tid] = bv;
        g_besti[blockIdx.y * NQ + q0 + tid] = bi;
    }
}

// ---------------------------------------------------------------------------
// k_gather: combine strips, write quantized output, loss partials, histogram.
// ---------------------------------------------------------------------------
__global__ void k_gather(const float* __restrict__ X, const float* __restrict__ E,
                         float* __restrict__ out) {
    __shared__ float red[256];
    const int n = blockIdx.x;
    const int d = threadIdx.x;
    float v0 = g_bestv[n], v1 = g_bestv[NQ + n];
    int idx = (v1 < v0) ? g_besti[NQ + n] : g_besti[n];   // tie -> strip 0 (lower idx)
    float q = E[(size_t)idx * DIM + d];
    float x = X[(size_t)n * DIM + d];
    float diff = q - x;
    out[(size_t)n * DIM + d] = x + diff;   // STE numerics
    red[d] = diff * diff;
    __syncthreads();
    #pragma unroll
    for (int off = 128; off > 0; off >>= 1) {
        if (d < off) red[d] += red[d + off];
        __syncthreads();
    }
    if (d == 0) {
        g_partial[n] = red[0];
        atomicAdd(&g_counts[idx], 1);
    }
}

// ---------------------------------------------------------------------------
// k_final: deterministic loss + perplexity.
// ---------------------------------------------------------------------------
__global__ void k_final(float* __restrict__ out, int out_size) {
    __shared__ float sm[1024];
    const int t = threadIdx.x;

    float s = 0.f;
    for (int i = t; i < NQ; i += 1024) s += g_partial[i];
    sm[t] = s;
    __syncthreads();
    #pragma unroll
    for (int off = 512; off > 0; off >>= 1) {
        if (t < off) sm[t] += sm[t + off];
        __syncthreads();
    }
    const float total = sm[0];
    __syncthreads();

    float hsum = 0.f;
    for (int i = t; i < NC; i += 1024) {
        float p = (float)g_counts[i] * (1.0f / (float)NQ);
        hsum += p * logf(p + 1e-10f);
    }
    sm[t] = hsum;
    __syncthreads();
    #pragma unroll
    for (int off = 512; off > 0; off >>= 1) {
        if (t < off) sm[t] += sm[t + off];
        __syncthreads();
    }

    if (t == 0) {
        float mean_sq = total / (float)((size_t)NQ * DIM);
        float loss = mean_sq + 0.25f * mean_sq;
        float perplexity = expf(-sm[0]);
        if (out_size >= NQ * DIM + 2) {
            out[(size_t)NQ * DIM]     = loss;
            out[(size_t)NQ * DIM + 1] = perplexity;
        }
    }
}

// ---------------------------------------------------------------------------
extern "C" void kernel_launch(void* const* d_in, const int* in_sizes, int n_in,
                              void* d_out, int out_size) {
    const float* X = (const float*)d_in[0];   // [32,256,256] -> [8192,256]
    const float* E = (const float*)d_in[1];   // [8192,256]
    float* out = (float*)d_out;

    cudaFuncSetAttribute(k_gemm, cudaFuncAttributeMaxDynamicSharedMemorySize, SMEM_BYTES);

    k_init<<<NC / 8, 256>>>(E);
    k_gemm<<<dim3(64, 2), 256, SMEM_BYTES>>>(X, E);
    k_gather<<<NQ, 256>>>(X, E, out);
    k_final<<<1, 1024>>>(out, out_size);
}

// round 5
// speedup vs baseline: 3.2493x; 1.2639x over previous
#include <cuda_runtime.h>
#include <cuda_fp16.h>
#include <math.h>
#include <stdint.h>

#define NQ 8192
#define NC 8192
#define DIM 256

// g_esplit: per (ctile 0..63, kchunk 0..7) a 16KB SMEM image: 1024 uint4.
// uint4 at [n*8 + ((g16*4+tig)^((n&1)<<2))] = {H2(k0),L2(k0),H2(k0+8),L2(k0+8)}
// where within-chunk k = g16*16 + {2*tig, 2*tig+1, 8+2*tig, 9+2*tig}.
__device__ uint4 g_esplit[64 * 8 * 1024];   // 8 MB
__device__ float g_enorm[NC];
__device__ int   g_counts[NC];
__device__ float g_partial[NQ];
__device__ float g_bestv[2 * NQ];
__device__ int   g_besti[2 * NQ];

#define XS_U4 0                 // X tile: 128 rows x 64 uint4 (1KB/row) = 128KB
#define ES_U4 8192              // E chunks: 2 x 1024 uint4 = 32KB
#define SMEM_BYTES ((8192 + 2048) * 16)   // 163840 B

// ---------------------------------------------------------------------------
__device__ __forceinline__ void mma16(float* c, uint32_t a0, uint32_t a1,
                                      uint32_t a2, uint32_t a3,
                                      uint32_t b0, uint32_t b1) {
    asm volatile(
        "mma.sync.aligned.m16n8k16.row.col.f32.f16.f16.f32 "
        "{%0,%1,%2,%3}, {%4,%5,%6,%7}, {%8,%9}, {%0,%1,%2,%3};"
        : "+f"(c[0]), "+f"(c[1]), "+f"(c[2]), "+f"(c[3])
        : "r"(a0), "r"(a1), "r"(a2), "r"(a3), "r"(b0), "r"(b1));
}

__device__ __forceinline__ void split_h2(float v0, float v1,
                                         uint32_t& hi2, uint32_t& lo2) {
    __half h0 = __float2half_rn(v0);
    __half h1 = __float2half_rn(v1);
    __half l0 = __float2half_rn(v0 - __half2float(h0));
    __half l1 = __float2half_rn(v1 - __half2float(h1));
    __half2 hh = __halves2half2(h0, h1);
    __half2 ll = __halves2half2(l0, l1);
    hi2 = *(uint32_t*)&hh;
    lo2 = *(uint32_t*)&ll;
}

// ---------------------------------------------------------------------------
// k_split: one block per codebook row. Computes ||e||^2, zeroes histogram,
// writes fp16 hi/lo split in the SMEM-image layout.
// ---------------------------------------------------------------------------
__global__ void k_split(const float* __restrict__ E) {
    __shared__ float buf[256];
    __shared__ float red[256];
    const int row = blockIdx.x;
    const int t = threadIdx.x;
    float v = E[(size_t)row * DIM + t];
    buf[t] = v;
    red[t] = v * v;
    if (row < 32) g_counts[row * 256 + t] = 0;
    __syncthreads();
    #pragma unroll
    for (int off = 128; off > 0; off >>= 1) {
        if (t < off) red[t] += red[t + off];
        __syncthreads();
    }
    if (t == 0) g_enorm[row] = red[0];

    if (t < 128) {
        float v0 = buf[2 * t], v1 = buf[2 * t + 1];
        uint32_t h2, l2;
        split_h2(v0, v1, h2, l2);
        const int kc  = t >> 4;            // k chunk 0..7
        const int g16 = (t >> 3) & 1;      // k16 group within chunk
        const int p   = t & 7;             // k-pair within group
        const int tig = p & 3;
        const int h8  = p >> 2;
        const int n   = row & 127;
        const int ctg = row >> 7;
        const int s   = (g16 * 4 + tig) ^ ((n & 1) << 2);
        uint32_t* dst = (uint32_t*)&g_esplit[(ctg * 8 + kc) * 1024 + n * 8 + s];
        dst[h8 * 2]     = h2;
        dst[h8 * 2 + 1] = l2;
    }
}

// ---------------------------------------------------------------------------
// k_gemm: 3xFP16 mma.sync distance GEMM + fused per-thread argmin.
// Grid (64 q-tiles, 2 strips) x 256 threads. CTA: 128 q x 4096 codes.
// 8 warps = 4(m: 32 rows) x 2(n: 64 cols); thread tile via m16n8k16 frags.
// ---------------------------------------------------------------------------
__global__ __launch_bounds__(256, 1) void k_gemm(const float* __restrict__ X) {
    extern __shared__ uint4 smem_u4[];

    const int tid   = threadIdx.x;
    const int lane  = tid & 31;
    const int wid   = tid >> 5;
    const int warpm = wid & 3;
    const int warpn = wid >> 2;
    const int gid   = lane >> 2;          // 0..7
    const int tig   = lane & 3;           // 0..3
    const int q0    = blockIdx.x * 128;
    const int strip = blockIdx.y;
    const int ro    = gid & 1;            // row/col parity for swizzle

    // ---- load + split X tile into SMEM images ----
    #pragma unroll
    for (int i = 0; i < 32; i++) {
        int idx = tid + i * 256;          // 0..8191 float4 slots
        int r = idx >> 6;
        int j = idx & 63;
        float4 v = *(const float4*)(X + (size_t)(q0 + r) * DIM + j * 4);
        int g16 = j >> 2;
        int p0  = (j & 3) * 2;            // pair index {0,2,4,6}
        int tg0 = p0 & 3;
        int h8  = p0 >> 2;
        int rsw = (r & 1) << 2;
        uint32_t h2a, l2a, h2b, l2b;
        split_h2(v.x, v.y, h2a, l2a);
        split_h2(v.z, v.w, h2b, l2b);
        uint32_t* d0 = (uint32_t*)&smem_u4[r * 64 + ((g16 * 4 + tg0) ^ rsw)];
        uint32_t* d1 = (uint32_t*)&smem_u4[r * 64 + ((g16 * 4 + tg0 + 1) ^ rsw)];
        d0[h8 * 2] = h2a;  d0[h8 * 2 + 1] = l2a;
        d1[h8 * 2] = h2b;  d1[h8 * 2 + 1] = l2b;
    }

    // ---- prologue: stage E chunk 0 ----
    {
        const uint4* src = g_esplit + (size_t)(strip * 32) * 8 * 1024;
        #pragma unroll
        for (int j = 0; j < 4; j++)
            smem_u4[ES_U4 + tid + j * 256] = src[tid + j * 256];
    }
    __syncthreads();

    float best[4];
    int   bidx[4];
    #pragma unroll
    for (int i = 0; i < 4; i++) { best[i] = INFINITY; bidx[i] = 0; }

    const int cbase0 = strip * 4096;

    for (int ct = 0; ct < 32; ct++) {
        float c[2][8][4];
        #pragma unroll
        for (int mt = 0; mt < 2; mt++)
            #pragma unroll
            for (int nt = 0; nt < 8; nt++)
                #pragma unroll
                for (int r = 0; r < 4; r++) c[mt][nt][r] = 0.f;

        for (int kc = 0; kc < 8; kc++) {
            const int cc = ct * 8 + kc;
            const int buf = cc & 1;

            // prefetch next chunk image into regs
            uint4 pref[4];
            const bool hasnext = (cc < 255);
            if (hasnext) {
                const uint4* src = g_esplit +
                    (size_t)((strip * 32 + ((cc + 1) >> 3)) * 8 + ((cc + 1) & 7)) * 1024;
                #pragma unroll
                for (int j = 0; j < 4; j++) pref[j] = src[tid + j * 256];
            }

            // ---- compute on staged buffer ----
            const uint4* EsB = smem_u4 + ES_U4 + buf * 1024;
            #pragma unroll
            for (int gg = 0; gg < 2; gg++) {
                uint4 Ar[2][2];
                #pragma unroll
                for (int mt = 0; mt < 2; mt++) {
                    const int r = warpm * 32 + mt * 16 + gid;
                    const int sA = ((2 * kc + gg) * 4 + tig) ^ (ro << 2);
                    Ar[mt][0] = smem_u4[r * 64 + sA];
                    Ar[mt][1] = smem_u4[(r + 8) * 64 + sA];
                }
                const int sB = (gg * 4 + tig) ^ (ro << 2);
                #pragma unroll
                for (int nt = 0; nt < 8; nt++) {
                    const int n = warpn * 64 + nt * 8 + gid;
                    uint4 B = EsB[n * 8 + sB];
                    #pragma unroll
                    for (int mt = 0; mt < 2; mt++) {
                        // hi*hi, hi*lo, lo*hi
                        mma16(c[mt][nt], Ar[mt][0].x, Ar[mt][1].x, Ar[mt][0].z, Ar[mt][1].z, B.x, B.z);
                        mma16(c[mt][nt], Ar[mt][0].x, Ar[mt][1].x, Ar[mt][0].z, Ar[mt][1].z, B.y, B.w);
                        mma16(c[mt][nt], Ar[mt][0].y, Ar[mt][1].y, Ar[mt][0].w, Ar[mt][1].w, B.x, B.z);
                    }
                }
            }

            // ---- stage prefetched chunk ----
            if (hasnext) {
                uint4* dst = smem_u4 + ES_U4 + (buf ^ 1) * 1024;
                #pragma unroll
                for (int j = 0; j < 4; j++) dst[tid + j * 256] = pref[j];
            }
            __syncthreads();
        }

        // ---- fused argmin epilogue (regs only) ----
        const int cb = cbase0 + ct * 128 + warpn * 64;
        #pragma unroll
        for (int nt = 0; nt < 8; nt++) {
            const int col0 = cb + nt * 8 + tig * 2;
            const float en0 = __ldg(&g_enorm[col0]);
            const float en1 = __ldg(&g_enorm[col0 + 1]);
            #pragma unroll
            for (int mt = 0; mt < 2; mt++) {
                float d;
                d = fmaf(-2.f, c[mt][nt][0], en0);
                if (d < best[mt * 2 + 0]) { best[mt * 2 + 0] = d; bidx[mt * 2 + 0] = col0; }
                d = fmaf(-2.f, c[mt][nt][1], en1);
                if (d < best[mt * 2 + 0]) { best[mt * 2 + 0] = d; bidx[mt * 2 + 0] = col0 + 1; }
                d = fmaf(-2.f, c[mt][nt][2], en0);
                if (d < best[mt * 2 + 1]) { best[mt * 2 + 1] = d; bidx[mt * 2 + 1] = col0; }
                d = fmaf(-2.f, c[mt][nt][3], en1);
                if (d < best[mt * 2 + 1]) { best[mt * 2 + 1] = d; bidx[mt * 2 + 1] = col0 + 1; }
            }
        }
    }

    // ---- cross-thread argmin reduce: 8 contributors per query row ----
    __syncthreads();
    float* rv = (float*)(smem_u4 + ES_U4);          // 128*8 floats
    int*   ri = (int*)(smem_u4 + ES_U4) + 1024;     // 128*8 ints
    const int slot = warpn * 4 + tig;
    #pragma unroll
    for (int mt = 0; mt < 2; mt++)
        #pragma unroll
        for (int rh = 0; rh < 2; rh++) {
            const int row = warpm * 32 + mt * 16 + rh * 8 + gid;
            rv[row * 8 + slot] = best[mt * 2 + rh];
            ri[row * 8 + slot] = bidx[mt * 2 + rh];
        }
    __syncthreads();
    if (tid < 128) {
        float bv = rv[tid * 8];
        int   bi = ri[tid * 8];
        #pragma unroll
        for (int s = 1; s < 8; s++) {
            float v = rv[tid * 8 + s];
            int   i = ri[tid * 8 + s];
            if (v < bv || (v == bv && i < bi)) { bv = v; bi = i; }
        }
        g_bestv[strip * NQ + q0 + tid] = bv;
        g_besti[strip * NQ + q0 + tid] = bi;
    }
}

// ---------------------------------------------------------------------------
// k_gather: combine strips, write quantized output, loss partials, histogram.
// ---------------------------------------------------------------------------
__global__ void k_gather(const float* __restrict__ X, const float* __restrict__ E,
                         float* __restrict__ out) {
    __shared__ float red[256];
    const int n = blockIdx.x;
    const int d = threadIdx.x;
    float v0 = g_bestv[n], v1 = g_bestv[NQ + n];
    int idx = (v1 < v0) ? g_besti[NQ + n] : g_besti[n];   // tie -> strip 0 (lower idx)
    float q = E[(size_t)idx * DIM + d];
    float x = X[(size_t)n * DIM + d];
    float diff = q - x;
    out[(size_t)n * DIM + d] = x + diff;   // STE numerics
    red[d] = diff * diff;
    __syncthreads();
    #pragma unroll
    for (int off = 128; off > 0; off >>= 1) {
        if (d < off) red[d] += red[d + off];
        __syncthreads();
    }
    if (d == 0) {
        g_partial[n] = red[0];
        atomicAdd(&g_counts[idx], 1);
    }
}

// ---------------------------------------------------------------------------
// k_final: deterministic loss + perplexity.
// ---------------------------------------------------------------------------
__global__ void k_final(float* __restrict__ out, int out_size) {
    __shared__ float sm[1024];
    const int t = threadIdx.x;

    float s = 0.f;
    for (int i = t; i < NQ; i += 1024) s += g_partial[i];
    sm[t] = s;
    __syncthreads();
    #pragma unroll
    for (int off = 512; off > 0; off >>= 1) {
        if (t < off) sm[t] += sm[t + off];
        __syncthreads();
    }
    const float total = sm[0];
    __syncthreads();

    float hsum = 0.f;
    for (int i = t; i < NC; i += 1024) {
        float p = (float)g_counts[i] * (1.0f / (float)NQ);
        hsum += p * logf(p + 1e-10f);
    }
    sm[t] = hsum;
    __syncthreads();
    #pragma unroll
    for (int off = 512; off > 0; off >>= 1) {
        if (t < off) sm[t] += sm[t + off];
        __syncthreads();
    }

    if (t == 0) {
        float mean_sq = total / (float)((size_t)NQ * DIM);
        float loss = mean_sq + 0.25f * mean_sq;
        float perplexity = expf(-sm[0]);
        if (out_size >= NQ * DIM + 2) {
            out[(size_t)NQ * DIM]     = loss;
            out[(size_t)NQ * DIM + 1] = perplexity;
        }
    }
}

// ---------------------------------------------------------------------------
extern "C" void kernel_launch(void* const* d_in, const int* in_sizes, int n_in,
                              void* d_out, int out_size) {
    const float* X = (const float*)d_in[0];   // [32,256,256] -> [8192,256]
    const float* E = (const float*)d_in[1];   // [8192,256]
    float* out = (float*)d_out;

    cudaFuncSetAttribute(k_gemm, cudaFuncAttributeMaxDynamicSharedMemorySize, SMEM_BYTES);

    k_split<<<NC, 256>>>(E);
    k_gemm<<<dim3(64, 2), 256, SMEM_BYTES>>>(X);
    k_gather<<<NQ, 256>>>(X, E, out);
    k_final<<<1, 1024>>>(out, out_size);
}

// round 6
// speedup vs baseline: 3.5786x; 1.1013x over previous
#include <cuda_runtime.h>
#include <cuda_fp16.h>
#include <math.h>
#include <stdint.h>

#define NQ 8192
#define NC 8192
#define DIM 256

// g_esplit: per (n256-tile 0..31, kchunk 0..7) a 32KB SMEM image: 2048 uint4.
// uint4 at [n*8 + ((g16*4+tig)^((n&1)<<2))] = {H2(k0),L2(k0),H2(k0+8),L2(k0+8)},
// within-chunk k = g16*16 + {2*tig, 2*tig+1, 8+2*tig, 9+2*tig}, n = code & 255.
__device__ uint4 g_esplit[32 * 8 * 2048];   // 8 MB
__device__ float g_enorm[NC];
__device__ int   g_counts[NC];
__device__ float g_partial[NQ];
__device__ float g_bestv[2 * NQ];
__device__ int   g_besti[2 * NQ];

#define ES_U4 8192                          // X: 8192 uint4 (128KB), then 3 E stages
#define STAGE_U4 2048                       // 32KB per stage
#define SMEM_BYTES ((8192 + 3 * 2048) * 16) // 229376 B

// ---------------------------------------------------------------------------
__device__ __forceinline__ void mma16(float* c, uint32_t a0, uint32_t a1,
                                      uint32_t a2, uint32_t a3,
                                      uint32_t b0, uint32_t b1) {
    asm volatile(
        "mma.sync.aligned.m16n8k16.row.col.f32.f16.f16.f32 "
        "{%0,%1,%2,%3}, {%4,%5,%6,%7}, {%8,%9}, {%0,%1,%2,%3};"
        : "+f"(c[0]), "+f"(c[1]), "+f"(c[2]), "+f"(c[3])
        : "r"(a0), "r"(a1), "r"(a2), "r"(a3), "r"(b0), "r"(b1));
}

__device__ __forceinline__ void split_h2(float v0, float v1,
                                         uint32_t& hi2, uint32_t& lo2) {
    __half h0 = __float2half_rn(v0);
    __half h1 = __float2half_rn(v1);
    __half l0 = __float2half_rn(v0 - __half2float(h0));
    __half l1 = __float2half_rn(v1 - __half2float(h1));
    __half2 hh = __halves2half2(h0, h1);
    __half2 ll = __halves2half2(l0, l1);
    hi2 = *(uint32_t*)&hh;
    lo2 = *(uint32_t*)&ll;
}

__device__ __forceinline__ void cp16(uint32_t daddr, const void* src) {
    asm volatile("cp.async.cg.shared.global [%0], [%1], 16;" :: "r"(daddr), "l"(src));
}
__device__ __forceinline__ uint32_t smem_u32(const void* p) {
    uint32_t a;
    asm("{ .reg .u64 t; cvta.to.shared.u64 t, %1; cvt.u32.u64 %0, t; }" : "=r"(a) : "l"(p));
    return a;
}

// ---------------------------------------------------------------------------
// k_split: one block per codebook row. ||e||^2, zero histogram, fp16 hi/lo
// split into the 256-wide SMEM-image layout.
// ---------------------------------------------------------------------------
__global__ void k_split(const float* __restrict__ E) {
    __shared__ float buf[256];
    __shared__ float red[256];
    const int row = blockIdx.x;
    const int t = threadIdx.x;
    float v = E[(size_t)row * DIM + t];
    buf[t] = v;
    red[t] = v * v;
    if (row < 32) g_counts[row * 256 + t] = 0;
    __syncthreads();
    #pragma unroll
    for (int off = 128; off > 0; off >>= 1) {
        if (t < off) red[t] += red[t + off];
        __syncthreads();
    }
    if (t == 0) g_enorm[row] = red[0];

    if (t < 128) {
        float v0 = buf[2 * t], v1 = buf[2 * t + 1];
        uint32_t h2, l2;
        split_h2(v0, v1, h2, l2);
        const int kc  = t >> 4;            // k chunk 0..7
        const int g16 = (t >> 3) & 1;      // k16 group within chunk
        const int p   = t & 7;             // k-pair within group
        const int tig = p & 3;
        const int h8  = p >> 2;
        const int n   = row & 255;
        const int ntg = row >> 8;          // n256 tile 0..31
        const int s   = (g16 * 4 + tig) ^ ((n & 1) << 2);
        uint32_t* dst = (uint32_t*)&g_esplit[(ntg * 8 + kc) * 2048 + n * 8 + s];
        dst[h8 * 2]     = h2;
        dst[h8 * 2 + 1] = l2;
    }
}

// ---------------------------------------------------------------------------
// k_gemm: 3xFP16 mma.sync distance GEMM + fused argmin.
// Grid (64 q-tiles, 2 strips) x 256 threads. CTA tile 128q x 256n x 16 ctiles.
// 8 warps = 2(m: 64 rows) x 4(n: 64 cols); warp tile 64x64 via m16n8k16.
// E chunks streamed with cp.async, 3-stage ring, one sync per k32.
// ---------------------------------------------------------------------------
__global__ __launch_bounds__(256, 1) void k_gemm(const float* __restrict__ X) {
    extern __shared__ uint4 smem_u4[];

    const int tid   = threadIdx.x;
    const int lane  = tid & 31;
    const int wid   = tid >> 5;
    const int warpm = wid & 1;            // 0..1, 64 rows each
    const int warpn = wid >> 1;           // 0..3, 64 cols each
    const int gid   = lane >> 2;          // 0..7
    const int tig   = lane & 3;           // 0..3
    const int q0    = blockIdx.x * 128;
    const int strip = blockIdx.y;
    const int ro    = gid & 1;

    const uint32_t es_base = smem_u32(smem_u4 + ES_U4);
    const uint4* esrc0 = g_esplit + (size_t)(strip * 16) * 8 * 2048;

    // ---- prologue: async-stage chunks 0,1 ----
    #pragma unroll
    for (int j = 0; j < 8; j++)
        cp16(es_base + (uint32_t)(tid + j * 256) * 16, esrc0 + tid + j * 256);
    asm volatile("cp.async.commit_group;" ::: "memory");
    #pragma unroll
    for (int j = 0; j < 8; j++)
        cp16(es_base + (uint32_t)(STAGE_U4 + tid + j * 256) * 16,
             esrc0 + 2048 + tid + j * 256);
    asm volatile("cp.async.commit_group;" ::: "memory");

    // ---- load + split X tile into SMEM image (overlaps cp.async) ----
    #pragma unroll
    for (int i = 0; i < 32; i++) {
        int idx = tid + i * 256;          // 0..8191 float4 slots
        int r = idx >> 6;
        int j = idx & 63;
        float4 v = *(const float4*)(X + (size_t)(q0 + r) * DIM + j * 4);
        int g16 = j >> 2;
        int p0  = (j & 3) * 2;
        int tg0 = p0 & 3;
        int h8  = p0 >> 2;
        int rsw = (r & 1) << 2;
        uint32_t h2a, l2a, h2b, l2b;
        split_h2(v.x, v.y, h2a, l2a);
        split_h2(v.z, v.w, h2b, l2b);
        uint32_t* d0 = (uint32_t*)&smem_u4[r * 64 + ((g16 * 4 + tg0) ^ rsw)];
        uint32_t* d1 = (uint32_t*)&smem_u4[r * 64 + ((g16 * 4 + tg0 + 1) ^ rsw)];
        d0[h8 * 2] = h2a;  d0[h8 * 2 + 1] = l2a;
        d1[h8 * 2] = h2b;  d1[h8 * 2 + 1] = l2b;
    }

    float best[8];
    int   bidx[8];
    #pragma unroll
    for (int i = 0; i < 8; i++) { best[i] = INFINITY; bidx[i] = 0; }

    const int cbase0 = strip * 4096;

    for (int ct = 0; ct < 16; ct++) {
        float c[4][8][4];
        #pragma unroll
        for (int mt = 0; mt < 4; mt++)
            #pragma unroll
            for (int nt = 0; nt < 8; nt++)
                #pragma unroll
                for (int r = 0; r < 4; r++) c[mt][nt][r] = 0.f;

        for (int kc = 0; kc < 8; kc++) {
            const int cc = ct * 8 + kc;

            // chunk cc arrived (for every thread after the sync)
            asm volatile("cp.async.wait_group 1;" ::: "memory");
            __syncthreads();

            // issue chunk cc+2 into stage (cc+2)%3 (last read at iter cc-1)
            if (cc + 2 < 128) {
                const uint32_t db = es_base + (uint32_t)(((cc + 2) % 3) * STAGE_U4) * 16;
                const uint4* src = esrc0 + (size_t)(cc + 2) * 2048;
                #pragma unroll
                for (int j = 0; j < 8; j++)
                    cp16(db + (uint32_t)(tid + j * 256) * 16, src + tid + j * 256);
            }
            asm volatile("cp.async.commit_group;" ::: "memory");

            // ---- compute on stage cc%3 ----
            const uint4* EsB = smem_u4 + ES_U4 + (cc % 3) * STAGE_U4;
            #pragma unroll
            for (int gg = 0; gg < 2; gg++) {
                uint4 Ar0[4], Ar1[4];
                const int sA = ((2 * kc + gg) * 4 + tig) ^ (ro << 2);
                #pragma unroll
                for (int mt = 0; mt < 4; mt++) {
                    const int r = warpm * 64 + mt * 16 + gid;
                    Ar0[mt] = smem_u4[r * 64 + sA];
                    Ar1[mt] = smem_u4[(r + 8) * 64 + sA];
                }
                const int sB = (gg * 4 + tig) ^ (ro << 2);
                #pragma unroll
                for (int nt = 0; nt < 8; nt++) {
                    const int n = warpn * 64 + nt * 8 + gid;
                    uint4 B = EsB[n * 8 + sB];
                    #pragma unroll
                    for (int mt = 0; mt < 4; mt++) {
                        mma16(c[mt][nt], Ar0[mt].x, Ar1[mt].x, Ar0[mt].z, Ar1[mt].z, B.x, B.z);
                        mma16(c[mt][nt], Ar0[mt].x, Ar1[mt].x, Ar0[mt].z, Ar1[mt].z, B.y, B.w);
                        mma16(c[mt][nt], Ar0[mt].y, Ar1[mt].y, Ar0[mt].w, Ar1[mt].w, B.x, B.z);
                    }
                }
            }
        }

        // ---- fused argmin epilogue (regs only) ----
        const int cb = cbase0 + ct * 256 + warpn * 64;
        #pragma unroll
        for (int nt = 0; nt < 8; nt++) {
            const int col0 = cb + nt * 8 + tig * 2;
            const float en0 = __ldg(&g_enorm[col0]);
            const float en1 = __ldg(&g_enorm[col0 + 1]);
            #pragma unroll
            for (int mt = 0; mt < 4; mt++) {
                float d;
                d = fmaf(-2.f, c[mt][nt][0], en0);
                if (d < best[mt * 2 + 0]) { best[mt * 2 + 0] = d; bidx[mt * 2 + 0] = col0; }
                d = fmaf(-2.f, c[mt][nt][1], en1);
                if (d < best[mt * 2 + 0]) { best[mt * 2 + 0] = d; bidx[mt * 2 + 0] = col0 + 1; }
                d = fmaf(-2.f, c[mt][nt][2], en0);
                if (d < best[mt * 2 + 1]) { best[mt * 2 + 1] = d; bidx[mt * 2 + 1] = col0; }
                d = fmaf(-2.f, c[mt][nt][3], en1);
                if (d < best[mt * 2 + 1]) { best[mt * 2 + 1] = d; bidx[mt * 2 + 1] = col0 + 1; }
            }
        }
    }

    // ---- cross-thread argmin reduce: 16 contributors per query row ----
    __syncthreads();
    float* rv = (float*)(smem_u4 + ES_U4);          // 128*16 floats
    int*   ri = (int*)(smem_u4 + ES_U4) + 2048;     // 128*16 ints
    const int slot = warpn * 4 + tig;
    #pragma unroll
    for (int mt = 0; mt < 4; mt++)
        #pragma unroll
        for (int rh = 0; rh < 2; rh++) {
            const int row = warpm * 64 + mt * 16 + rh * 8 + gid;
            rv[row * 16 + slot] = best[mt * 2 + rh];
            ri[row * 16 + slot] = bidx[mt * 2 + rh];
        }
    __syncthreads();
    if (tid < 128) {
        float bv = rv[tid * 16];
        int   bi = ri[tid * 16];
        #pragma unroll
        for (int s = 1; s < 16; s++) {
            float v = rv[tid * 16 + s];
            int   i = ri[tid * 16 + s];
            if (v < bv || (v == bv && i < bi)) { bv = v; bi = i; }
        }
        g_bestv[strip * NQ + q0 + tid] = bv;
        g_besti[strip * NQ + q0 + tid] = bi;
    }
}

// ---------------------------------------------------------------------------
// k_gather: warp per query row. Combine strips, quantized output, loss
// partials, histogram. grid = 1024 x 256 threads.
// ---------------------------------------------------------------------------
__global__ void k_gather(const float* __restrict__ X, const float* __restrict__ E,
                         float* __restrict__ out) {
    const int w = threadIdx.x >> 5;
    const int lane = threadIdx.x & 31;
    const int n = blockIdx.x * 8 + w;
    float v0 = g_bestv[n], v1 = g_bestv[NQ + n];
    int idx = (v1 < v0) ? g_besti[NQ + n] : g_besti[n];   // tie -> strip 0
    const float4* qe = (const float4*)(E + (size_t)idx * DIM);
    const float4* xr = (const float4*)(X + (size_t)n * DIM);
    float4* o = (float4*)(out + (size_t)n * DIM);
    float s = 0.f;
    #pragma unroll
    for (int h = 0; h < 2; h++) {
        int j = lane + h * 32;
        float4 q = qe[j], x = xr[j];
        float dx = q.x - x.x, dy = q.y - x.y, dz = q.z - x.z, dw = q.w - x.w;
        float4 r;
        r.x = x.x + dx; r.y = x.y + dy; r.z = x.z + dz; r.w = x.w + dw;
        o[j] = r;
        s += dx * dx + dy * dy + dz * dz + dw * dw;
    }
    #pragma unroll
    for (int off = 16; off > 0; off >>= 1)
        s += __shfl_down_sync(0xffffffffu, s, off);
    if (lane == 0) {
        g_partial[n] = s;
        atomicAdd(&g_counts[idx], 1);
    }
}

// ---------------------------------------------------------------------------
// k_final: deterministic loss + perplexity.
// ---------------------------------------------------------------------------
__global__ void k_final(float* __restrict__ out, int out_size) {
    __shared__ float sm[1024];
    const int t = threadIdx.x;

    float s = 0.f;
    for (int i = t; i < NQ; i += 1024) s += g_partial[i];
    sm[t] = s;
    __syncthreads();
    #pragma unroll
    for (int off = 512; off > 0; off >>= 1) {
        if (t < off) sm[t] += sm[t + off];
        __syncthreads();
    }
    const float total = sm[0];
    __syncthreads();

    float hsum = 0.f;
    for (int i = t; i < NC; i += 1024) {
        float p = (float)g_counts[i] * (1.0f / (float)NQ);
        hsum += p * logf(p + 1e-10f);
    }
    sm[t] = hsum;
    __syncthreads();
    #pragma unroll
    for (int off = 512; off > 0; off >>= 1) {
        if (t < off) sm[t] += sm[t + off];
        __syncthreads();
    }

    if (t == 0) {
        float mean_sq = total / (float)((size_t)NQ * DIM);
        float loss = mean_sq + 0.25f * mean_sq;
        float perplexity = expf(-sm[0]);
        if (out_size >= NQ * DIM + 2) {
            out[(size_t)NQ * DIM]     = loss;
            out[(size_t)NQ * DIM + 1] = perplexity;
        }
    }
}

// ---------------------------------------------------------------------------
extern "C" void kernel_launch(void* const* d_in, const int* in_sizes, int n_in,
                              void* d_out, int out_size) {
    const float* X = (const float*)d_in[0];   // [32,256,256] -> [8192,256]
    const float* E = (const float*)d_in[1];   // [8192,256]
    float* out = (float*)d_out;

    cudaFuncSetAttribute(k_gemm, cudaFuncAttributeMaxDynamicSharedMemorySize, SMEM_BYTES);

    k_split<<<NC, 256>>>(E);
    k_gemm<<<dim3(64, 2), 256, SMEM_BYTES>>>(X);
    k_gather<<<1024, 256>>>(X, E, out);
    k_final<<<1, 1024>>>(out, out_size);
}